// round 5
// baseline (speedup 1.0000x reference)
#include <cuda_runtime.h>

// out[b,i,j,d] = x[b,i,j,d] + W[d, bin] + bias[d],  bin = clip(i-j,-31,31)+31
// B=2, L=512, D=128. x/out: 256 MB each (fp32). Pure HBM stream.
//
// Inputs (metadata order): d_in[0]=x (f32), d_in[1]=idx (i64, unused),
//                          d_in[2]=W (f32 [128,63]), d_in[3]=b (f32 [128])
//
// R4: single fused kernel. Each block covers 32 rows (fixed i, j in
// [j0,j0+32)); it builds its 32-bin-row slice of the rel-emb table in
// shared memory (coalesced W reads: for fixed d the 32 bins are contiguous),
// hidden behind the front-batched DRAM loads. No prep kernel, 1 graph node.

#define L_DIM   512
#define D_DIM   128
#define NBINS   63
#define TOTAL_F4 (2 * L_DIM * L_DIM * (D_DIM / 4))   // 16,777,216
#define VPT 4
#define TPB 256
#define ROWS_PER_BLOCK ((TPB * VPT) / (D_DIM / 4))   // 32
#define ROW_STRIDE 132                                // floats, padded (132 % 4 == 0)

__global__ __launch_bounds__(TPB)
void add_rel_fused_kernel(const float4* __restrict__ x,
                          float4* __restrict__ out,
                          const float* __restrict__ W,
                          const float* __restrict__ bias) {
    __shared__ float s_emb[ROWS_PER_BLOCK * ROW_STRIDE];   // 16.9 KB

    const int tid    = threadIdx.x;
    const int warpId = tid >> 5;
    const int lane   = tid & 31;
    const int base   = blockIdx.x * (TPB * VPT) + tid;

    // Front-batch the 4 independent DRAM loads (MLP=4); smem fill + barrier
    // overlap their latency.
    float4 xv[VPT];
    #pragma unroll
    for (int k = 0; k < VPT; k++)
        xv[k] = __ldcs(&x[base + k * TPB]);

    // Block geometry: 32 consecutive rows, fixed i, j in [j0, j0+32).
    const int row0 = blockIdx.x * ROWS_PER_BLOCK;
    const int i    = (row0 >> 9) & (L_DIM - 1);
    const int j0   = row0 & (L_DIM - 1);

    // Fill smem table: lane = jo (local j), warp iterates over d.
    // For fixed d, lanes read W[d*63 + bin(jo)] with bins consecutive or
    // clipped-equal -> coalesced (1-2 lines, L1/L2-hot: W is only 32 KB).
    int rel = i - (j0 + lane);
    rel = max(-(NBINS / 2), min(NBINS / 2, rel));
    const int bin = rel + NBINS / 2;                       // 0..62
    #pragma unroll
    for (int d = warpId; d < D_DIM; d += TPB / 32)
        s_emb[lane * ROW_STRIDE + d] = W[d * NBINS + bin] + bias[d];

    __syncthreads();

    // Main loop: per-thread jo = warpId + 8k, d4 = lane (both trivial).
    // LDS.128 with ROW_STRIDE=132 floats is bank-conflict-free.
    const float4* s4 = reinterpret_cast<const float4*>(s_emb);
    #pragma unroll
    for (int k = 0; k < VPT; k++) {
        const int jo = warpId + (TPB / 32) * k;
        const float4 rv = s4[jo * (ROW_STRIDE / 4) + lane];
        float4 ov;
        ov.x = xv[k].x + rv.x;
        ov.y = xv[k].y + rv.y;
        ov.z = xv[k].z + rv.z;
        ov.w = xv[k].w + rv.w;
        __stcs(&out[base + k * TPB], ov);
    }
}

extern "C" void kernel_launch(void* const* d_in, const int* in_sizes, int n_in,
                              void* d_out, int out_size) {
    const float* x    = (const float*)d_in[0];
    const float* W    = (const float*)d_in[2];
    const float* bias = (const float*)d_in[3];
    float* out        = (float*)d_out;

    add_rel_fused_kernel<<<TOTAL_F4 / (TPB * VPT), TPB>>>(
        (const float4*)x, (float4*)out, W, bias);
}

// round 9
// speedup vs baseline: 1.4831x; 1.4831x over previous
#include <cuda_runtime.h>

// out[b,i,j,d] = x[b,i,j,d] + W[d, bin] + bias[d],  bin = clip(i-j,-31,31)+31
// B=2, L=512, D=128. x/out: 256 MB each (fp32). Pure HBM stream.
//
// Inputs (metadata order): d_in[0]=x (f32), d_in[1]=idx (i64, unused),
//                          d_in[2]=W (f32 [128,63]), d_in[3]=b (f32 [128])
//
// R5: R2 structure (prep kernel -> __device__ table, main stream kernel with
// VPT=4 front-batched loads) + PDL: main kernel prelaunches under the prep
// kernel, issues its x DRAM loads, then griddepcontrol.wait before touching
// the table. Prep duration + launch ramp are hidden.

#define L_DIM   512
#define D_DIM   128
#define NBINS   63
#define TOTAL_F4 (2 * L_DIM * L_DIM * (D_DIM / 4))   // 16,777,216
#define VPT 4
#define TPB 256

// relemb[bin][d] = W[d][bin] + b[d]  (63*128 floats = 32 KB)
__device__ float4 g_relemb[NBINS * (D_DIM / 4)];

// Coalesced linear read of W (8064 floats), scattered 4B writes into the
// tiny table (lands in L2). 63 blocks for launch-ramp parallelism.
__global__ __launch_bounds__(128)
void build_relemb_kernel(const float* __restrict__ W,
                         const float* __restrict__ bias) {
    int t = blockIdx.x * blockDim.x + threadIdx.x;    // 0 .. 8063
    if (t >= NBINS * D_DIM) return;
    int d   = t / NBINS;                              // W is [128, 63] row-major
    int bin = t - d * NBINS;
    float v = W[t] + bias[d];
    reinterpret_cast<float*>(g_relemb)[bin * D_DIM + d] = v;
}

__global__ __launch_bounds__(TPB)
void add_rel_kernel(const float4* __restrict__ x, float4* __restrict__ out) {
    int base = blockIdx.x * (TPB * VPT) + threadIdx.x;

    // Front-batch the 4 independent DRAM loads (MLP=4). These do NOT depend
    // on the prep kernel, so issue them before the grid-dependency wait.
    float4 xv[VPT];
    #pragma unroll
    for (int k = 0; k < VPT; k++)
        xv[k] = __ldcs(&x[base + k * TPB]);

    // Wait for the prep kernel to complete (PDL). Its table writes are
    // visible after this point.
    asm volatile("griddepcontrol.wait;" ::: "memory");

    float4 rv[VPT];
    #pragma unroll
    for (int k = 0; k < VPT; k++) {
        int g   = base + k * TPB;
        int d4  = g & 31;
        int row = g >> 5;                         // b*L*L + i*L + j
        int j   = row & (L_DIM - 1);
        int i   = (row >> 9) & (L_DIM - 1);
        int rel = i - j;
        rel = max(-(NBINS / 2), min(NBINS / 2, rel));
        int bin = rel + NBINS / 2;                // 0..62
        rv[k] = g_relemb[bin * 32 + d4];          // L1/L2-resident table hit
    }

    #pragma unroll
    for (int k = 0; k < VPT; k++) {
        float4 ov;
        ov.x = xv[k].x + rv[k].x;
        ov.y = xv[k].y + rv[k].y;
        ov.z = xv[k].z + rv[k].z;
        ov.w = xv[k].w + rv[k].w;
        __stcs(&out[base + k * TPB], ov);
    }
}

extern "C" void kernel_launch(void* const* d_in, const int* in_sizes, int n_in,
                              void* d_out, int out_size) {
    const float* x    = (const float*)d_in[0];
    const float* W    = (const float*)d_in[2];
    const float* bias = (const float*)d_in[3];
    float* out        = (float*)d_out;

    build_relemb_kernel<<<NBINS, 128>>>(W, bias);

    // Main kernel with programmatic stream serialization: blocks prelaunch
    // while prep runs; griddepcontrol.wait gates the table reads.
    cudaLaunchConfig_t cfg = {};
    cfg.gridDim  = dim3(TOTAL_F4 / (TPB * VPT));
    cfg.blockDim = dim3(TPB);
    cfg.dynamicSmemBytes = 0;
    cfg.stream = 0;
    cudaLaunchAttribute attrs[1];
    attrs[0].id = cudaLaunchAttributeProgrammaticStreamSerialization;
    attrs[0].val.programmaticStreamSerializationAllowed = 1;
    cfg.attrs = attrs;
    cfg.numAttrs = 1;

    const float4* x4 = (const float4*)x;
    float4* o4       = (float4*)out;
    cudaLaunchKernelEx(&cfg, add_rel_kernel, x4, o4);
}